// round 1
// baseline (speedup 1.0000x reference)
#include <cuda_runtime.h>

#define B_   32768
#define FEAT 4096
#define XLD  4097
#define HID  2048
#define PROJ 512
#define NOUT 3

#define BM 128
#define BN 128
#define BK 16
#define TILES_M (B_/BM + 2)

// ---------------- scratch (device globals, no allocation) ----------------
__device__ int   g_cnt[2];
__device__ int   g_cnt2[2];
__device__ int   g_base_oth;
__device__ int   g_pos2row[B_ + 256];
__device__ float g_H[(size_t)(B_ + 256) * HID];   // hidden activations (permuted rows)
__device__ float g_Z[(size_t)B_ * PROJ];          // z in ORIGINAL row order

// ---------------- setup kernels: partition rows by flag ----------------
__global__ void k_zero() { g_cnt[0] = 0; g_cnt[1] = 0; }

__global__ void k_count(const float* __restrict__ x) {
    int r = blockIdx.x * blockDim.x + threadIdx.x;
    if (r < B_) {
        int g = (x[(size_t)r * XLD + FEAT] > 0.5f) ? 0 : 1;
        atomicAdd(&g_cnt[g], 1);
    }
}

__global__ void k_mid() {
    g_base_oth = ((g_cnt[0] + BM - 1) / BM) * BM;
    g_cnt2[0] = 0; g_cnt2[1] = 0;
}

__global__ void k_assign(const float* __restrict__ x) {
    int r = blockIdx.x * blockDim.x + threadIdx.x;
    if (r < B_) {
        int g = (x[(size_t)r * XLD + FEAT] > 0.5f) ? 0 : 1;
        int idx = atomicAdd(&g_cnt2[g], 1);
        int pos = g ? (g_base_oth + idx) : idx;
        g_pos2row[pos] = r;
    }
}

// ---------------- GEMM1: H = relu(gather(feat) @ W1_sel + b1_sel) ----------------
// A: x rows gathered by permutation (stride 4097, scalar loads — odd stride breaks float4)
// C: g_H, permuted-position indexed
__global__ __launch_bounds__(256) void gemm1_kernel(
    const float* __restrict__ x,
    const float* __restrict__ W1n, const float* __restrict__ b1n,
    const float* __restrict__ W1o, const float* __restrict__ b1o)
{
    __shared__ float As[2][BK][BM];
    __shared__ float Bs[2][BK][BN];

    const int n_nat = g_cnt[0];
    const int n_oth = g_cnt[1];
    const int nat_tiles = (n_nat + BM - 1) / BM;
    const int bm = blockIdx.x;
    const int bn = blockIdx.y;

    int grp, prow0, nrows;
    if (bm < nat_tiles) {
        grp = 0; prow0 = bm * BM; nrows = min(BM, n_nat - prow0);
    } else {
        int bm2 = bm - nat_tiles;
        if (bm2 * BM >= n_oth) return;
        grp = 1; prow0 = nat_tiles * BM + bm2 * BM;
        nrows = min(BM, n_oth - bm2 * BM);
    }
    const float* __restrict__ W    = grp ? W1o : W1n;
    const float* __restrict__ bias = grp ? b1o : b1n;

    const int t    = threadIdx.x;
    const int arow = t >> 1;
    const int ak0  = (t & 1) * 8;
    const float* aptr = nullptr;
    if (arow < nrows) {
        int orig = g_pos2row[prow0 + arow];
        aptr = x + (size_t)orig * XLD;
    }
    const int bk_a = t >> 5;            // 0..7
    const int bn4  = (t & 31) * 4;      // 0..124
    const float* __restrict__ Wb = W + bn * BN + bn4;

    const int tm = (t >> 4) * 8;
    const int tn = (t & 15) * 8;

    float acc[8][8];
    #pragma unroll
    for (int i = 0; i < 8; i++)
        #pragma unroll
        for (int j = 0; j < 8; j++) acc[i][j] = 0.f;

    // prologue: tile kt=0 -> buf 0
    {
        #pragma unroll
        for (int j = 0; j < 8; j++)
            As[0][ak0 + j][arow] = aptr ? aptr[ak0 + j] : 0.f;
        float4 v0 = *(const float4*)(Wb + (size_t)bk_a * HID);
        float4 v1 = *(const float4*)(Wb + (size_t)(bk_a + 8) * HID);
        *(float4*)&Bs[0][bk_a][bn4]     = v0;
        *(float4*)&Bs[0][bk_a + 8][bn4] = v1;
    }
    __syncthreads();

    for (int kt = 0; kt < FEAT; kt += BK) {
        const int buf = (kt / BK) & 1;
        const bool more = (kt + BK < FEAT);

        // prefetch next tile into registers (hide LDG behind compute)
        float  ra[8];
        float4 rb0, rb1;
        if (more) {
            const int k2 = kt + BK;
            #pragma unroll
            for (int j = 0; j < 8; j++)
                ra[j] = aptr ? aptr[k2 + ak0 + j] : 0.f;
            rb0 = *(const float4*)(Wb + (size_t)(k2 + bk_a) * HID);
            rb1 = *(const float4*)(Wb + (size_t)(k2 + bk_a + 8) * HID);
        }

        #pragma unroll
        for (int kk = 0; kk < BK; kk++) {
            float4 a0 = *(const float4*)&As[buf][kk][tm];
            float4 a1 = *(const float4*)&As[buf][kk][tm + 4];
            float4 b0 = *(const float4*)&Bs[buf][kk][tn];
            float4 b1 = *(const float4*)&Bs[buf][kk][tn + 4];
            float a[8] = {a0.x,a0.y,a0.z,a0.w,a1.x,a1.y,a1.z,a1.w};
            float b[8] = {b0.x,b0.y,b0.z,b0.w,b1.x,b1.y,b1.z,b1.w};
            #pragma unroll
            for (int i = 0; i < 8; i++)
                #pragma unroll
                for (int j = 0; j < 8; j++)
                    acc[i][j] = fmaf(a[i], b[j], acc[i][j]);
        }

        if (more) {
            const int nb = buf ^ 1;
            #pragma unroll
            for (int j = 0; j < 8; j++)
                As[nb][ak0 + j][arow] = ra[j];
            *(float4*)&Bs[nb][bk_a][bn4]     = rb0;
            *(float4*)&Bs[nb][bk_a + 8][bn4] = rb1;
        }
        __syncthreads();
    }

    // epilogue: bias + relu -> g_H (permuted position)
    #pragma unroll
    for (int i = 0; i < 8; i++) {
        const int pr = tm + i;
        if (pr < nrows) {
            float* hrow = g_H + (size_t)(prow0 + pr) * HID + bn * BN + tn;
            #pragma unroll
            for (int j = 0; j < 8; j++) {
                float v = acc[i][j] + bias[bn * BN + tn + j];
                hrow[j] = fmaxf(v, 0.f);
            }
        }
    }
}

// ---------------- GEMM2: Z = H @ W2_sel + b2_sel (scatter to original rows) ----------------
__global__ __launch_bounds__(256) void gemm2_kernel(
    const float* __restrict__ W2n, const float* __restrict__ b2n,
    const float* __restrict__ W2o, const float* __restrict__ b2o)
{
    __shared__ float As[2][BK][BM];
    __shared__ float Bs[2][BK][BN];

    const int n_nat = g_cnt[0];
    const int n_oth = g_cnt[1];
    const int nat_tiles = (n_nat + BM - 1) / BM;
    const int bm = blockIdx.x;
    const int bn = blockIdx.y;

    int grp, prow0, nrows;
    if (bm < nat_tiles) {
        grp = 0; prow0 = bm * BM; nrows = min(BM, n_nat - prow0);
    } else {
        int bm2 = bm - nat_tiles;
        if (bm2 * BM >= n_oth) return;
        grp = 1; prow0 = nat_tiles * BM + bm2 * BM;
        nrows = min(BM, n_oth - bm2 * BM);
    }
    const float* __restrict__ W    = grp ? W2o : W2n;
    const float* __restrict__ bias = grp ? b2o : b2n;

    const int t    = threadIdx.x;
    const int arow = t >> 1;
    const int ak0  = (t & 1) * 8;
    const float* aptr = (arow < nrows) ? (g_H + (size_t)(prow0 + arow) * HID) : nullptr;

    const int bk_a = t >> 5;
    const int bn4  = (t & 31) * 4;
    const float* __restrict__ Wb = W + bn * BN + bn4;

    const int tm = (t >> 4) * 8;
    const int tn = (t & 15) * 8;

    float acc[8][8];
    #pragma unroll
    for (int i = 0; i < 8; i++)
        #pragma unroll
        for (int j = 0; j < 8; j++) acc[i][j] = 0.f;

    {
        float4 a0 = aptr ? *(const float4*)(aptr + ak0)     : make_float4(0,0,0,0);
        float4 a1 = aptr ? *(const float4*)(aptr + ak0 + 4) : make_float4(0,0,0,0);
        As[0][ak0+0][arow]=a0.x; As[0][ak0+1][arow]=a0.y; As[0][ak0+2][arow]=a0.z; As[0][ak0+3][arow]=a0.w;
        As[0][ak0+4][arow]=a1.x; As[0][ak0+5][arow]=a1.y; As[0][ak0+6][arow]=a1.z; As[0][ak0+7][arow]=a1.w;
        float4 v0 = *(const float4*)(Wb + (size_t)bk_a * PROJ);
        float4 v1 = *(const float4*)(Wb + (size_t)(bk_a + 8) * PROJ);
        *(float4*)&Bs[0][bk_a][bn4]     = v0;
        *(float4*)&Bs[0][bk_a + 8][bn4] = v1;
    }
    __syncthreads();

    for (int kt = 0; kt < HID; kt += BK) {
        const int buf = (kt / BK) & 1;
        const bool more = (kt + BK < HID);

        float4 pa0, pa1, rb0, rb1;
        if (more) {
            const int k2 = kt + BK;
            pa0 = aptr ? *(const float4*)(aptr + k2 + ak0)     : make_float4(0,0,0,0);
            pa1 = aptr ? *(const float4*)(aptr + k2 + ak0 + 4) : make_float4(0,0,0,0);
            rb0 = *(const float4*)(Wb + (size_t)(k2 + bk_a) * PROJ);
            rb1 = *(const float4*)(Wb + (size_t)(k2 + bk_a + 8) * PROJ);
        }

        #pragma unroll
        for (int kk = 0; kk < BK; kk++) {
            float4 a0 = *(const float4*)&As[buf][kk][tm];
            float4 a1 = *(const float4*)&As[buf][kk][tm + 4];
            float4 b0 = *(const float4*)&Bs[buf][kk][tn];
            float4 b1 = *(const float4*)&Bs[buf][kk][tn + 4];
            float a[8] = {a0.x,a0.y,a0.z,a0.w,a1.x,a1.y,a1.z,a1.w};
            float b[8] = {b0.x,b0.y,b0.z,b0.w,b1.x,b1.y,b1.z,b1.w};
            #pragma unroll
            for (int i = 0; i < 8; i++)
                #pragma unroll
                for (int j = 0; j < 8; j++)
                    acc[i][j] = fmaf(a[i], b[j], acc[i][j]);
        }

        if (more) {
            const int nb = buf ^ 1;
            As[nb][ak0+0][arow]=pa0.x; As[nb][ak0+1][arow]=pa0.y; As[nb][ak0+2][arow]=pa0.z; As[nb][ak0+3][arow]=pa0.w;
            As[nb][ak0+4][arow]=pa1.x; As[nb][ak0+5][arow]=pa1.y; As[nb][ak0+6][arow]=pa1.z; As[nb][ak0+7][arow]=pa1.w;
            *(float4*)&Bs[nb][bk_a][bn4]     = rb0;
            *(float4*)&Bs[nb][bk_a + 8][bn4] = rb1;
        }
        __syncthreads();
    }

    // epilogue: + bias, scatter to original row order (no relu; z is raw)
    #pragma unroll
    for (int i = 0; i < 8; i++) {
        const int pr = tm + i;
        if (pr < nrows) {
            const int orig = g_pos2row[prow0 + pr];
            float* zrow = g_Z + (size_t)orig * PROJ + bn * BN + tn;
            #pragma unroll
            for (int j = 0; j < 8; j++)
                zrow[j] = acc[i][j] + bias[bn * BN + tn + j];
        }
    }
}

// ---------------- finalize: norm, z_normalized, logits ----------------
__global__ __launch_bounds__(128) void k_final(
    const float* __restrict__ x,
    const float* __restrict__ Wcn, const float* __restrict__ bcn,
    const float* __restrict__ Wco, const float* __restrict__ bco,
    float* __restrict__ out)
{
    const int row = blockIdx.x;
    const bool nat = x[(size_t)row * XLD + FEAT] > 0.5f;
    const float* __restrict__ Wc = nat ? Wcn : Wco;
    const float* __restrict__ bc = nat ? bcn : bco;

    const int t = threadIdx.x;
    const float* zr = g_Z + (size_t)row * PROJ;

    float zv[4];
    float ss = 0.f, l0 = 0.f, l1 = 0.f, l2 = 0.f;
    #pragma unroll
    for (int i = 0; i < 4; i++) {
        const int k = t + i * 128;
        const float z = zr[k];
        zv[i] = z;
        ss = fmaf(z, z, ss);
        const float rz = fmaxf(z, 0.f);
        l0 = fmaf(rz, Wc[k * 3 + 0], l0);
        l1 = fmaf(rz, Wc[k * 3 + 1], l1);
        l2 = fmaf(rz, Wc[k * 3 + 2], l2);
    }
    #pragma unroll
    for (int o = 16; o > 0; o >>= 1) {
        ss += __shfl_down_sync(0xFFFFFFFFu, ss, o);
        l0 += __shfl_down_sync(0xFFFFFFFFu, l0, o);
        l1 += __shfl_down_sync(0xFFFFFFFFu, l1, o);
        l2 += __shfl_down_sync(0xFFFFFFFFu, l2, o);
    }
    __shared__ float red[4][4];
    __shared__ float inv_s;
    const int w = t >> 5, lane = t & 31;
    if (lane == 0) { red[w][0] = ss; red[w][1] = l0; red[w][2] = l1; red[w][3] = l2; }
    __syncthreads();
    if (t == 0) {
        float S  = red[0][0] + red[1][0] + red[2][0] + red[3][0];
        float L0 = red[0][1] + red[1][1] + red[2][1] + red[3][1];
        float L1 = red[0][2] + red[1][2] + red[2][2] + red[3][2];
        float L2 = red[0][3] + red[1][3] + red[2][3] + red[3][3];
        float norm = sqrtf(S);
        inv_s = 1.f / fmaxf(norm, 1e-12f);
        float* lg = out + (size_t)B_ * PROJ + (size_t)row * NOUT;
        lg[0] = L0 + bc[0];
        lg[1] = L1 + bc[1];
        lg[2] = L2 + bc[2];
    }
    __syncthreads();
    const float inv = inv_s;
    #pragma unroll
    for (int i = 0; i < 4; i++)
        out[(size_t)row * PROJ + t + i * 128] = zv[i] * inv;
}

// ---------------- launcher ----------------
extern "C" void kernel_launch(void* const* d_in, const int* in_sizes, int n_in,
                              void* d_out, int out_size) {
    const float* x   = (const float*)d_in[0];
    const float* W1n = (const float*)d_in[1];
    const float* b1n = (const float*)d_in[2];
    const float* W2n = (const float*)d_in[3];
    const float* b2n = (const float*)d_in[4];
    const float* Wcn = (const float*)d_in[5];
    const float* bcn = (const float*)d_in[6];
    const float* W1o = (const float*)d_in[7];
    const float* b1o = (const float*)d_in[8];
    const float* W2o = (const float*)d_in[9];
    const float* b2o = (const float*)d_in[10];
    const float* Wco = (const float*)d_in[11];
    const float* bco = (const float*)d_in[12];
    float* out = (float*)d_out;

    k_zero<<<1, 1>>>();
    k_count<<<B_ / 256, 256>>>(x);
    k_mid<<<1, 1>>>();
    k_assign<<<B_ / 256, 256>>>(x);

    dim3 g1(TILES_M, HID / BN);
    gemm1_kernel<<<g1, 256>>>(x, W1n, b1n, W1o, b1o);

    dim3 g2(TILES_M, PROJ / BN);
    gemm2_kernel<<<g2, 256>>>(W2n, b2n, W2o, b2o);

    k_final<<<B_, 128>>>(x, Wcn, bcn, Wco, bco, out);
}